// round 16
// baseline (speedup 1.0000x reference)
#include <cuda_runtime.h>
#include <math.h>

#define LSEQ 1024
#define DMODEL 2048
#define NHQ 16
#define NHK 8
#define DHEAD 128
#define NCHUNK 16
#define CLEN 64
#define NITER 30
#define RIDGE_C 0.02f

__device__ __forceinline__ unsigned f2tf(float f) {
    unsigned r; asm("cvt.rna.tf32.f32 %0, %1;" : "=r"(r) : "f"(f)); return r;
}
__device__ __forceinline__ float f2tff(float f) {
    unsigned r; asm("cvt.rna.tf32.f32 %0, %1;" : "=r"(r) : "f"(f));
    return __uint_as_float(r);
}
#define MMA_TF32(acc, a0, a1, a2, a3, b0, b1)                               \
    asm volatile(                                                           \
        "mma.sync.aligned.m16n8k8.row.col.f32.tf32.tf32.f32 "               \
        "{%0,%1,%2,%3}, {%4,%5,%6,%7}, {%8,%9}, {%0,%1,%2,%3};"             \
        : "+f"((acc)[0]), "+f"((acc)[1]), "+f"((acc)[2]), "+f"((acc)[3])    \
        : "r"(a0), "r"(a1), "r"(a2), "r"(a3), "r"(b0), "r"(b1))

__device__ __forceinline__ void cp_async16(void* smem_dst, const void* gmem_src) {
    unsigned sa = (unsigned)__cvta_generic_to_shared(smem_dst);
    asm volatile("cp.async.ca.shared.global [%0], [%1], 16;" :: "r"(sa), "l"(gmem_src));
}
__device__ __forceinline__ void cp_commit() {
    asm volatile("cp.async.commit_group;");
}
template<int NWAIT>
__device__ __forceinline__ void cp_wait() {
    asm volatile("cp.async.wait_group %0;" :: "n"(NWAIT));
}

// ---------------- device scratch ----------------
__device__ float g_pqp[2][LSEQ * 2048];
__device__ float g_pkp[2][LSEQ * 1024];
__device__ float g_pvp[2][LSEQ * 1024];
__device__ float g_gpp[2][LSEQ * 2048];
__device__ float g_outp[2][LSEQ * 2048];
__device__ float g_q [LSEQ * 2048];
__device__ float g_k [LSEQ * 1024];
__device__ float g_v [LSEQ * 1024];
__device__ float g_gpart[4][LSEQ][48];
__device__ float g_glog [LSEQ * NHQ];
__device__ float g_beta [LSEQ * NHQ];
__device__ float g_alpha[LSEQ * NHQ];
__device__ float g_cs[NHQ * NCHUNK * CLEN];
__device__ float g_G [NHQ * NCHUNK];
__device__ float g_dgv[NHQ * NCHUNK];
__device__ float g_dH[NHQ * NCHUNK * DHEAD * DHEAD];
__device__ float g_dB[NHQ * NCHUNK * DHEAD * DHEAD];
__device__ float g_H0[NHQ * NCHUNK * DHEAD * DHEAD];
__device__ float g_B0[NHQ * NCHUNK * DHEAD * DHEAD];
__device__ float g_X [NHQ * NCHUNK * DHEAD * DHEAD];
__device__ float g_on[LSEQ * 2048];
__device__ float g_xr [LSEQ * 2048];

// -- tf32 GEMM: 128x128 tile, KTILE=32, m16n8k8, 3-stage cp.async --
// A pre-rounded tf32 (CVT-free); B raw fp32 (CVT at fragment load).
#define GST (3 * (128 * 36 + 32 * 136) * 4)   // 107520 bytes

struct SmemTF32 {
    float As[3][128][36];
    float Bs[3][32][136];
};

__device__ __forceinline__ void gemm_tf32_core(
    const float* __restrict__ A, const float* __restrict__ B, float* __restrict__ C,
    int N, int Kfull, int koff, int klen, int bm, int bn, SmemTF32& s)
{
    const int tid = threadIdx.x;
    const int warp = tid >> 5, lane = tid & 31;
    const int wy = warp >> 1, wx = warp & 1;
    const int m0 = wy * 32, n0 = wx * 64;
    const int r = lane >> 2, c = lane & 3;

    float acc[2][8][4];
#pragma unroll
    for (int mt = 0; mt < 2; mt++)
#pragma unroll
        for (int nt = 0; nt < 8; nt++)
#pragma unroll
            for (int i = 0; i < 4; i++) acc[mt][nt][i] = 0.f;

    const int ar = tid >> 3;           // 0..31 (rows +0,+32,+64,+96)
    const int ak = (tid & 7) * 4;      // 0..28
    const int bk = tid >> 5;           // 0..7 (kk +0,+8,+16,+24)
    const int bn4 = (tid & 31) * 4;    // 0..124

    const float* Apb = A + (size_t)(bm + ar) * Kfull + koff + ak;
    const float* Bpb = B + (size_t)(koff + bk) * N + bn + bn4;
    const size_t Arow32 = (size_t)32 * Kfull;
    const size_t Brow8 = (size_t)8 * N;

    const int nk = klen >> 5;
    // prologue: stage tiles 0 and 1 as separate groups
#pragma unroll
    for (int pt = 0; pt < 2; pt++) {
        if (pt < nk) {
            int k0 = pt << 5;
#pragma unroll
            for (int p = 0; p < 4; p++) {
                cp_async16(&s.As[pt][ar + 32 * p][ak], Apb + k0 + (size_t)p * Arow32);
                cp_async16(&s.Bs[pt][bk + 8 * p][bn4], Bpb + (size_t)k0 * N + (size_t)p * Brow8);
            }
            cp_commit();
        }
    }

    for (int t = 0; t < nk; t++) {
        cp_wait<1>();          // tile t complete (t+1 may still be in flight)
        __syncthreads();
        if (t + 2 < nk) {
            const int nb = (t + 2) % 3;
            int k0 = (t + 2) << 5;
#pragma unroll
            for (int p = 0; p < 4; p++) {
                cp_async16(&s.As[nb][ar + 32 * p][ak], Apb + k0 + (size_t)p * Arow32);
                cp_async16(&s.Bs[nb][bk + 8 * p][bn4], Bpb + (size_t)k0 * N + (size_t)p * Brow8);
            }
            cp_commit();
        }
        const int cur = t % 3;
#pragma unroll
        for (int ks = 0; ks < 4; ks++) {
            const int kk = ks * 8;
            unsigned a[2][4];
#pragma unroll
            for (int mt = 0; mt < 2; mt++) {
                int mr = m0 + mt * 16;
                a[mt][0] = __float_as_uint(s.As[cur][mr + r][kk + c]);
                a[mt][1] = __float_as_uint(s.As[cur][mr + r + 8][kk + c]);
                a[mt][2] = __float_as_uint(s.As[cur][mr + r][kk + c + 4]);
                a[mt][3] = __float_as_uint(s.As[cur][mr + r + 8][kk + c + 4]);
            }
#pragma unroll
            for (int nt = 0; nt < 8; nt++) {
                unsigned b0 = f2tf(s.Bs[cur][kk + c][n0 + nt * 8 + r]);
                unsigned b1 = f2tf(s.Bs[cur][kk + c + 4][n0 + nt * 8 + r]);
#pragma unroll
                for (int mt = 0; mt < 2; mt++)
                    MMA_TF32(acc[mt][nt], a[mt][0], a[mt][1], a[mt][2], a[mt][3], b0, b1);
            }
        }
    }
#pragma unroll
    for (int mt = 0; mt < 2; mt++) {
        int mr = bm + m0 + mt * 16 + r;
#pragma unroll
        for (int nt = 0; nt < 8; nt++) {
            int col = bn + n0 + nt * 8 + 2 * c;
            *(float2*)(C + (size_t)mr * N + col) =
                make_float2(acc[mt][nt][0], acc[mt][nt][1]);
            *(float2*)(C + (size_t)(mr + 8) * N + col) =
                make_float2(acc[mt][nt][2], acc[mt][nt][3]);
        }
    }
}

// output projection, K-split 2 (z dim), partial outputs
__global__ __launch_bounds__(256) void sgemm_tf32(
    const float* __restrict__ A, const float* __restrict__ B)
{
    extern __shared__ char smraw[];
    const int kz = blockIdx.z;
    gemm_tf32_core(A, B, g_outp[kz], 2048, 2048, kz * 1024, 1024,
                   blockIdx.y * 128, blockIdx.x * 128, *(SmemTF32*)smraw);
}

__global__ void add_out(float* __restrict__ out)
{
    int i4 = blockIdx.x * 256 + threadIdx.x;   // 512K float4
    float4 a = *(const float4*)(g_outp[0] + (size_t)i4 * 4);
    float4 b = *(const float4*)(g_outp[1] + (size_t)i4 * 4);
    *(float4*)(out + (size_t)i4 * 4) =
        make_float4(a.x + b.x, a.y + b.y, a.z + b.z, a.w + b.w);
}

// fused projections, K-split 2 (z dim), partial outputs
__global__ __launch_bounds__(256) void proj_tf32(
    const float* __restrict__ Wq, const float* __restrict__ Wk,
    const float* __restrict__ Wv, const float* __restrict__ Wg)
{
    extern __shared__ char smraw[];
    const int bx = blockIdx.x, kz = blockIdx.z;
    const float* B; float* C; int N, bn;
    if (bx < 16)      { B = Wq; C = g_pqp[kz]; N = 2048; bn = bx * 128; }
    else if (bx < 24) { B = Wk; C = g_pkp[kz]; N = 1024; bn = (bx - 16) * 128; }
    else if (bx < 32) { B = Wv; C = g_pvp[kz]; N = 1024; bn = (bx - 24) * 128; }
    else              { B = Wg; C = g_gpp[kz]; N = 2048; bn = (bx - 32) * 128; }
    gemm_tf32_core(g_xr, B, C, N, DMODEL, kz * 1024, 1024,
                   blockIdx.y * 128, bn, *(SmemTF32*)smraw);
}

// ------- gates as GEMM (fp32) + side-effect: write tf32-rounded x -------
__global__ __launch_bounds__(256) void gates_mm(
    const float* __restrict__ x, const float* __restrict__ Wa,
    const float* __restrict__ Wb, const float* __restrict__ Wal)
{
    __shared__ float xs[16][132];
    __shared__ float Ws[16][52];
    const int bm = blockIdx.x * 128;
    const int k0 = blockIdx.y * 512;
    const int tid = threadIdx.x;
    const int row = tid >> 1, kq = (tid & 1) * 8;
    const int wk = tid >> 4, wh = tid & 15;
    const int ty = tid >> 3, tx = tid & 7;

    float acc[4][6];
#pragma unroll
    for (int i = 0; i < 4; i++)
#pragma unroll
        for (int j = 0; j < 6; j++) acc[i][j] = 0.f;

    for (int kt = 0; kt < 512; kt += 16) {
        const int kb = k0 + kt;
        float4 v0 = *(const float4*)(x + (size_t)(bm + row) * DMODEL + kb + kq);
        float4 v1 = *(const float4*)(x + (size_t)(bm + row) * DMODEL + kb + kq + 4);
        xs[kq + 0][row] = v0.x; xs[kq + 1][row] = v0.y;
        xs[kq + 2][row] = v0.z; xs[kq + 3][row] = v0.w;
        xs[kq + 4][row] = v1.x; xs[kq + 5][row] = v1.y;
        xs[kq + 6][row] = v1.z; xs[kq + 7][row] = v1.w;
        float4 r0 = make_float4(f2tff(v0.x), f2tff(v0.y), f2tff(v0.z), f2tff(v0.w));
        float4 r1 = make_float4(f2tff(v1.x), f2tff(v1.y), f2tff(v1.z), f2tff(v1.w));
        *(float4*)(g_xr + (size_t)(bm + row) * DMODEL + kb + kq)     = r0;
        *(float4*)(g_xr + (size_t)(bm + row) * DMODEL + kb + kq + 4) = r1;
        Ws[wk][wh]      = Wa[(size_t)(kb + wk) * NHQ + wh];
        Ws[wk][16 + wh] = Wb[(size_t)(kb + wk) * NHQ + wh];
        Ws[wk][32 + wh] = Wal[(size_t)(kb + wk) * NHQ + wh];
        __syncthreads();
#pragma unroll
        for (int kk = 0; kk < 16; kk++) {
            float a[4], b[6];
#pragma unroll
            for (int i = 0; i < 4; i++) a[i] = xs[kk][ty * 4 + i];
#pragma unroll
            for (int j = 0; j < 6; j++) b[j] = Ws[kk][tx * 6 + j];
#pragma unroll
            for (int i = 0; i < 4; i++)
#pragma unroll
                for (int j = 0; j < 6; j++) acc[i][j] += a[i] * b[j];
        }
        __syncthreads();
    }
#pragma unroll
    for (int i = 0; i < 4; i++)
#pragma unroll
        for (int j = 0; j < 6; j++)
            g_gpart[blockIdx.y][bm + ty * 4 + i][tx * 6 + j] = acc[i][j];
}

__global__ void gates_ep(
    const float* __restrict__ A_log, const float* __restrict__ dt_bias,
    const float* __restrict__ bb, const float* __restrict__ bal)
{
    int idx = blockIdx.x * 256 + threadIdx.x;
    if (idx >= LSEQ * 48) return;
    int t = idx / 48, j = idx % 48;
    float s = g_gpart[0][t][j] + g_gpart[1][t][j]
            + g_gpart[2][t][j] + g_gpart[3][t][j];
    if (j < 16) {
        float z = s + dt_bias[j];
        float sp = (z > 20.f) ? z : log1pf(expf(z));
        g_glog[t * NHQ + j] = -expf(A_log[j]) * sp;
    } else if (j < 32) {
        int h = j - 16;
        g_beta[t * NHQ + h] = 1.f / (1.f + expf(-(s + bb[h])));
    } else {
        int h = j - 32;
        g_alpha[t * NHQ + h] = 1.f / (1.f + expf(-(s + bal[h])));
    }
}

// ------ fused conv(4)+silu for q,k,v; sums the two K-split partials ------
__global__ void conv_all(const float* __restrict__ wq, const float* __restrict__ wk,
                         const float* __restrict__ wv)
{
    int idx = blockIdx.x * 256 + threadIdx.x;
    const float *in0, *in1, *w; float* out; int C; float scale; int id2;
    if (idx < LSEQ * 2048) {
        in0 = g_pqp[0]; in1 = g_pqp[1]; w = wq; out = g_q; C = 2048;
        scale = 0.08838834764831843f; id2 = idx;
    } else if (idx < LSEQ * 2048 + LSEQ * 1024) {
        in0 = g_pkp[0]; in1 = g_pkp[1]; w = wk; out = g_k; C = 1024;
        scale = 1.f; id2 = idx - LSEQ * 2048;
    } else {
        in0 = g_pvp[0]; in1 = g_pvp[1]; w = wv; out = g_v; C = 1024;
        scale = 1.f; id2 = idx - LSEQ * 2048 - LSEQ * 1024;
    }
    int t = id2 / C, c = id2 % C;
    float s = 0.f;
#pragma unroll
    for (int j = 0; j < 4; j++) {
        int tj = t - 3 + j;
        if (tj >= 0) {
            size_t o = (size_t)tj * C + c;
            s += (in0[o] + in1[o]) * w[c * 4 + j];
        }
    }
    out[id2] = s / (1.f + expf(-s)) * scale;
}

// ---------------- per-chunk cumsum ----------------
__global__ void cs_kernel()
{
    int id = threadIdx.x;
    int h = id >> 4, n = id & 15;
    float s = 0.f;
    for (int c = 0; c < CLEN; c++) {
        s += g_glog[(n * CLEN + c) * NHQ + h];
        g_cs[(h * NCHUNK + n) * CLEN + c] = s;
    }
    g_G[h * NCHUNK + n] = s;
    g_dgv[h * NCHUNK + n] = expf(s);
}

// -------- dH / dB gram increments via tf32 mma --------
#define DB_PAD 132
#define DB_SMEM ((2 * 64 * DB_PAD + 64) * 4)

__global__ __launch_bounds__(256, 1) void dhb_tf32()
{
    extern __shared__ float sm[];
    float* ksf = sm;
    float* vsf = sm + 64 * DB_PAD;
    float* ws  = sm + 2 * 64 * DB_PAD;
    const int mat = blockIdx.x;
    const int h = mat >> 4, n = mat & 15, hk = h >> 1;
    const int tid = threadIdx.x;
    for (int i = tid; i < CLEN * DHEAD; i += 256) {
        int c = i >> 7, d = i & 127;
        int t = n * CLEN + c;
        ksf[c * DB_PAD + d] = g_k[t * 1024 + hk * DHEAD + d];
        vsf[c * DB_PAD + d] = g_v[t * 1024 + hk * DHEAD + d];
    }
    if (tid < CLEN) {
        float G = g_G[mat];
        float cs = g_cs[mat * CLEN + tid];
        ws[tid] = expf(G - cs) * g_beta[(n * CLEN + tid) * NHQ + h];
    }
    __syncthreads();

    const int warp = tid >> 5, lane = tid & 31;
    const int m0 = warp * 16;
    const int fr = lane >> 2, fc = lane & 3;

    float accH[16][4], accB[16][4];
#pragma unroll
    for (int nt = 0; nt < 16; nt++)
#pragma unroll
        for (int i = 0; i < 4; i++) { accH[nt][i] = 0.f; accB[nt][i] = 0.f; }

#pragma unroll 1
    for (int ks8 = 0; ks8 < 8; ks8++) {
        const int kk = ks8 * 8;
        float w0 = ws[kk + fc], w1 = ws[kk + fc + 4];
        unsigned a0 = f2tf(w0 * ksf[(kk + fc) * DB_PAD + m0 + fr]);
        unsigned a1 = f2tf(w0 * ksf[(kk + fc) * DB_PAD + m0 + fr + 8]);
        unsigned a2 = f2tf(w1 * ksf[(kk + fc + 4) * DB_PAD + m0 + fr]);
        unsigned a3 = f2tf(w1 * ksf[(kk + fc + 4) * DB_PAD + m0 + fr + 8]);
#pragma unroll
        for (int nt = 0; nt < 16; nt++) {
            int cn = nt * 8 + fr;
            unsigned bh0 = f2tf(ksf[(kk + fc) * DB_PAD + cn]);
            unsigned bh1 = f2tf(ksf[(kk + fc + 4) * DB_PAD + cn]);
            MMA_TF32(accH[nt], a0, a1, a2, a3, bh0, bh1);
            unsigned bv0 = f2tf(vsf[(kk + fc) * DB_PAD + cn]);
            unsigned bv1 = f2tf(vsf[(kk + fc + 4) * DB_PAD + cn]);
            MMA_TF32(accB[nt], a0, a1, a2, a3, bv0, bv1);
        }
    }
    size_t base = (size_t)mat * DHEAD * DHEAD;
#pragma unroll
    for (int nt = 0; nt < 16; nt++) {
        int col = nt * 8 + 2 * fc;
        size_t r0 = base + (size_t)(m0 + fr) * 128 + col;
        size_t r1 = base + (size_t)(m0 + fr + 8) * 128 + col;
        *(float2*)&g_dH[r0] = make_float2(accH[nt][0], accH[nt][1]);
        *(float2*)&g_dH[r1] = make_float2(accH[nt][2], accH[nt][3]);
        *(float2*)&g_dB[r0] = make_float2(accB[nt][0], accB[nt][1]);
        *(float2*)&g_dB[r1] = make_float2(accB[nt][2], accB[nt][3]);
    }
}

// ---------------- inter-chunk scan ----------------
__global__ void scan_kernel()
{
    int idx = blockIdx.x * blockDim.x + threadIdx.x;
    int h = idx >> 14;
    int rem = idx & 16383;
    float hc = 0.f, bc = 0.f;
    for (int n = 0; n < NCHUNK; n++) {
        size_t off = (size_t)(h * NCHUNK + n) * 16384 + rem;
        g_H0[off] = hc;
        g_B0[off] = bc;
        float g = g_dgv[h * NCHUNK + n];
        hc = g * hc + g_dH[off];
        bc = g * bc + g_dB[off];
    }
}

// ------- Chebyshev solve -------
#define CH_APAD 132
#define CH_DPAD 136
#define CH_SMEM (128*CH_APAD*4 + 128*CH_DPAD*4)

__global__ __launch_bounds__(256, 1) void cheb_tf32()
{
    extern __shared__ char smemraw[];
    unsigned (*Ash)[CH_APAD] = (unsigned(*)[CH_APAD])smemraw;
    float (*dsh)[CH_DPAD] = (float(*)[CH_DPAD])(smemraw + 128 * CH_APAD * 4);
    __shared__ float red[128];
    __shared__ float s_lmax;

    const int mat = blockIdx.x;
    const int tid = threadIdx.x;
    const int warp = tid >> 5, lane = tid & 31;
    const int m0 = warp * 16;
    const int fr = lane >> 2, fc = lane & 3;
    const int ro = m0 + fr;
    const float* H0 = g_H0 + (size_t)mat * 16384;
    const float* B0p = g_B0 + (size_t)mat * 16384;

    for (int i = tid; i < 16384; i += 256) {
        int row = i >> 7, col = i & 127;
        float v = H0[i];
        if (row == col) { v += RIDGE_C; red[row] = v; }
        Ash[row][col] = f2tf(v);
    }
    __syncthreads();
    for (int s = 64; s > 0; s >>= 1) {
        if (tid < s) red[tid] += red[tid + s];
        __syncthreads();
    }
    if (tid == 0) s_lmax = red[0];
    __syncthreads();

    const float lmax = s_lmax;
    const float theta = (lmax + RIDGE_C) * 0.5f;
    const float delta = (lmax - RIDGE_C) * 0.5f;
    const float sigma1 = theta / delta;
    float rho = 1.f / sigma1;
    const float inv_theta = 1.f / theta;

    float r_[16][4], x_[16][4];
#pragma unroll
    for (int nt = 0; nt < 16; nt++) {
        int co = nt * 8 + 2 * fc;
        float2 b0 = *(const float2*)&B0p[ro * 128 + co];
        float2 b1 = *(const float2*)&B0p[(ro + 8) * 128 + co];
        r_[nt][0] = b0.x; r_[nt][1] = b0.y; r_[nt][2] = b1.x; r_[nt][3] = b1.y;
        x_[nt][0] = 0.f; x_[nt][1] = 0.f; x_[nt][2] = 0.f; x_[nt][3] = 0.f;
        *(float2*)&dsh[ro][co] = make_float2(
            f2tff(b0.x * inv_theta), f2tff(b0.y * inv_theta));
        *(float2*)&dsh[ro + 8][co] = make_float2(
            f2tff(b1.x * inv_theta), f2tff(b1.y * inv_theta));
    }
    __syncthreads();

    for (int it = 0; it < NITER; it++) {
        float acc[16][4];
#pragma unroll
        for (int nt = 0; nt < 16; nt++) {
            acc[nt][0] = 0.f; acc[nt][1] = 0.f; acc[nt][2] = 0.f; acc[nt][3] = 0.f;
        }
#pragma unroll 1
        for (int ks = 0; ks < 16; ks++) {
            const int kk = ks * 8;
            unsigned a0 = Ash[m0 + fr][kk + fc];
            unsigned a1 = Ash[m0 + fr + 8][kk + fc];
            unsigned a2 = Ash[m0 + fr][kk + fc + 4];
            unsigned a3 = Ash[m0 + fr + 8][kk + fc + 4];
#pragma unroll
            for (int nt = 0; nt < 16; nt++) {
                unsigned b0 = __float_as_uint(dsh[kk + fc][nt * 8 + fr]);
                unsigned b1 = __float_as_uint(dsh[kk + fc + 4][nt * 8 + fr]);
                MMA_TF32(acc[nt], a0, a1, a2, a3, b0, b1);
            }
        }
        __syncthreads();

        float rho_n = 1.f / (2.f * sigma1 - rho);
        float c1 = rho_n * rho;
        float c2 = 2.f * rho_n / delta;
#pragma unroll
        for (int nt = 0; nt < 16; nt++) {
            int co = nt * 8 + 2 * fc;
            float2 d0 = *(float2*)&dsh[ro][co];
            float2 d1 = *(float2*)&dsh[ro + 8][co];
            x_[nt][0] += d0.x; x_[nt][1] += d0.y;
            x_[nt][2] += d1.x; x_[nt][3] += d1.y;
            r_[nt][0] -= acc[nt][0]; r_[nt][1] -= acc[nt][1];
            r_[nt][2] -= acc[nt][2]; r_[nt][3] -= acc[nt][3];
            d0.x = f2tff(c1 * d0.x + c2 * r_[nt][0]);
            d0.y = f2tff(c1 * d0.y + c2 * r_[nt][1]);
            d1.x = f2tff(c1 * d1.x + c2 * r_[nt][2]);
            d1.y = f2tff(c1 * d1.y + c2 * r_[nt][3]);
            *(float2*)&dsh[ro][co]     = d0;
            *(float2*)&dsh[ro + 8][co] = d1;
        }
        rho = rho_n;
        __syncthreads();
    }

    float* Xp = g_X + (size_t)mat * 16384;
#pragma unroll
    for (int nt = 0; nt < 16; nt++) {
        int co = nt * 8 + 2 * fc;
        *(float2*)&Xp[ro * 128 + co]       = make_float2(x_[nt][0], x_[nt][1]);
        *(float2*)&Xp[(ro + 8) * 128 + co] = make_float2(x_[nt][2], x_[nt][3]);
    }
}

// ---- o: scores + inter + intra via tf32 mma, alpha*v, gated RMSNorm ----
#define OP 132
#define O_SMEM ((3 * 64 * OP + 128 * OP + 64 * OP) * 4)

__global__ __launch_bounds__(256, 1) void o_tf32(const float* __restrict__ norm_w)
{
    extern __shared__ float sm[];
    float* qs = sm;
    float* ks = sm + 64 * OP;
    float* vs = sm + 2 * 64 * OP;
    float* Xs = sm + 3 * 64 * OP;
    float* Os = sm + 3 * 64 * OP + 128 * OP;
    __shared__ float csh[CLEN], bsh[CLEN], ash[CLEN], expc[CLEN];
    const int mat = blockIdx.x;
    const int h = mat >> 4, n = mat & 15, hk = h >> 1;
    const int tid = threadIdx.x;
    const int warp = tid >> 5, lane = tid & 31;
    const int fr = lane >> 2, fc = lane & 3;

    for (int i = tid; i < CLEN * DHEAD; i += 256) {
        int c = i >> 7, d = i & 127;
        int t = n * CLEN + c;
        qs[c * OP + d] = g_q[t * 2048 + h * DHEAD + d];
        ks[c * OP + d] = g_k[t * 1024 + hk * DHEAD + d];
        vs[c * OP + d] = g_v[t * 1024 + hk * DHEAD + d];
    }
    for (int i = tid; i < 16384; i += 256) {
        int row = i >> 7, col = i & 127;
        Xs[row * OP + col] = g_X[(size_t)mat * 16384 + i];
    }
    if (tid < CLEN) {
        float cv = g_cs[mat * CLEN + tid];
        csh[tid] = cv;
        expc[tid] = expf(cv);
        int t = n * CLEN + tid;
        bsh[tid] = g_beta[t * NHQ + h];
        ash[tid] = g_alpha[t * NHQ + h];
    }
    __syncthreads();

    {
        const int m0 = (warp & 3) * 16, n0 = (warp >> 2) * 32;
        float sc[4][4];
#pragma unroll
        for (int nt = 0; nt < 4; nt++)
#pragma unroll
            for (int i = 0; i < 4; i++) sc[nt][i] = 0.f;
#pragma unroll 1
        for (int ks8 = 0; ks8 < 16; ks8++) {
            const int kk = ks8 * 8;
            unsigned a0 = f2tf(qs[(m0 + fr) * OP + kk + fc]);
            unsigned a1 = f2tf(qs[(m0 + fr + 8) * OP + kk + fc]);
            unsigned a2 = f2tf(qs[(m0 + fr) * OP + kk + fc + 4]);
            unsigned a3 = f2tf(qs[(m0 + fr + 8) * OP + kk + fc + 4]);
#pragma unroll
            for (int nt = 0; nt < 4; nt++) {
                int j = n0 + nt * 8 + fr;
                unsigned b0 = f2tf(ks[j * OP + kk + fc]);
                unsigned b1 = f2tf(ks[j * OP + kk + fc + 4]);
                MMA_TF32(sc[nt], a0, a1, a2, a3, b0, b1);
            }
        }
#pragma unroll
        for (int nt = 0; nt < 4; nt++) {
            int j0 = n0 + nt * 8 + 2 * fc;
            int c0 = m0 + fr, c1 = m0 + fr + 8;
#pragma unroll
            for (int e = 0; e < 4; e++) {
                int c = (e < 2) ? c0 : c1;
                int j = j0 + (e & 1);
                float v = 0.f;
                if (j <= c) v = sc[nt][e] * expf(csh[c] - csh[j]) * bsh[j];
                Os[c * OP + j] = v;
            }
        }
    }
    __syncthreads();

    {
        const int m0 = (warp & 3) * 16, n0 = (warp >> 2) * 64;
        float oa[8][4];
#pragma unroll
        for (int nt = 0; nt < 8; nt++)
#pragma unroll
            for (int i = 0; i < 4; i++) oa[nt][i] = 0.f;
        float e0 = expc[m0 + fr], e1 = expc[m0 + fr + 8];
#pragma unroll 1
        for (int ks8 = 0; ks8 < 16; ks8++) {
            const int kk = ks8 * 8;
            unsigned a0 = f2tf(qs[(m0 + fr) * OP + kk + fc] * e0);
            unsigned a1 = f2tf(qs[(m0 + fr + 8) * OP + kk + fc] * e1);
            unsigned a2 = f2tf(qs[(m0 + fr) * OP + kk + fc + 4] * e0);
            unsigned a3 = f2tf(qs[(m0 + fr + 8) * OP + kk + fc + 4] * e1);
#pragma unroll
            for (int nt = 0; nt < 8; nt++) {
                int cn = n0 + nt * 8 + fr;
                unsigned b0 = f2tf(Xs[(kk + fc) * OP + cn]);
                unsigned b1 = f2tf(Xs[(kk + fc + 4) * OP + cn]);
                MMA_TF32(oa[nt], a0, a1, a2, a3, b0, b1);
            }
        }
#pragma unroll 1
        for (int ks8 = 0; ks8 < 8; ks8++) {
            const int kk = ks8 * 8;
            unsigned a0 = f2tf(Os[(m0 + fr) * OP + kk + fc]);
            unsigned a1 = f2tf(Os[(m0 + fr + 8) * OP + kk + fc]);
            unsigned a2 = f2tf(Os[(m0 + fr) * OP + kk + fc + 4]);
            unsigned a3 = f2tf(Os[(m0 + fr + 8) * OP + kk + fc + 4]);
#pragma unroll
            for (int nt = 0; nt < 8; nt++) {
                int cn = n0 + nt * 8 + fr;
                unsigned b0 = f2tf(vs[(kk + fc) * OP + cn]);
                unsigned b1 = f2tf(vs[(kk + fc + 4) * OP + cn]);
                MMA_TF32(oa[nt], a0, a1, a2, a3, b0, b1);
            }
        }
        __syncthreads();
        int c0 = m0 + fr, c1 = m0 + fr + 8;
        float al0 = ash[c0], al1 = ash[c1];
#pragma unroll
        for (int nt = 0; nt < 8; nt++) {
            int col = n0 + nt * 8 + 2 * fc;
            Os[c0 * OP + col]     = oa[nt][0] + al0 * vs[c0 * OP + col];
            Os[c0 * OP + col + 1] = oa[nt][1] + al0 * vs[c0 * OP + col + 1];
            Os[c1 * OP + col]     = oa[nt][2] + al1 * vs[c1 * OP + col];
            Os[c1 * OP + col + 1] = oa[nt][3] + al1 * vs[c1 * OP + col + 1];
        }
    }
    __syncthreads();

    {
        const int ty = warp, tx = lane;
        const int f0 = tx * 4;
        float4 nw = *(const float4*)(norm_w + f0);
#pragma unroll
        for (int i = 0; i < 8; i++) {
            int c = ty * 8 + i;
            int t = n * CLEN + c;
            float4 ov = *(const float4*)&Os[c * OP + f0];
            float ss = ov.x * ov.x + ov.y * ov.y + ov.z * ov.z + ov.w * ov.w;
#pragma unroll
            for (int off = 16; off > 0; off >>= 1)
                ss += __shfl_xor_sync(0xFFFFFFFFu, ss, off);
            float rms = rsqrtf(ss * (1.f / 128.f) + 1e-6f);
            size_t go = (size_t)t * 2048 + h * 128 + f0;
            float4 g0 = *(const float4*)(g_gpp[0] + go);
            float4 g1 = *(const float4*)(g_gpp[1] + go);
            float4 gw = make_float4(g0.x + g1.x, g0.y + g1.y,
                                    g0.z + g1.z, g0.w + g1.w);
            float4 o;
            o.x = f2tff(ov.x * rms * nw.x * (gw.x / (1.f + expf(-gw.x))));
            o.y = f2tff(ov.y * rms * nw.y * (gw.y / (1.f + expf(-gw.y))));
            o.z = f2tff(ov.z * rms * nw.z * (gw.z / (1.f + expf(-gw.z))));
            o.w = f2tff(ov.w * rms * nw.w * (gw.w / (1.f + expf(-gw.w))));
            *(float4*)&g_on[go] = o;
        }
    }
}

// ---------------- launch ----------------
extern "C" void kernel_launch(void* const* d_in, const int* in_sizes, int n_in,
                              void* d_out, int out_size)
{
    const float* x      = (const float*)d_in[0];
    const float* Wq     = (const float*)d_in[1];
    const float* Wk     = (const float*)d_in[2];
    const float* Wv     = (const float*)d_in[3];
    const float* conv_q = (const float*)d_in[4];
    const float* conv_k = (const float*)d_in[5];
    const float* conv_v = (const float*)d_in[6];
    const float* Wa     = (const float*)d_in[7];
    const float* A_log  = (const float*)d_in[8];
    const float* dt_b   = (const float*)d_in[9];
    const float* Wb     = (const float*)d_in[10];
    const float* bb     = (const float*)d_in[11];
    const float* Wal    = (const float*)d_in[12];
    const float* bal    = (const float*)d_in[13];
    const float* Wg     = (const float*)d_in[14];
    const float* norm_w = (const float*)d_in[15];
    const float* Wo     = (const float*)d_in[16];
    float* out = (float*)d_out;

    float *on;
    cudaGetSymbolAddress((void**)&on, g_on);

    cudaFuncSetAttribute(proj_tf32, cudaFuncAttributeMaxDynamicSharedMemorySize, GST);
    cudaFuncSetAttribute(sgemm_tf32, cudaFuncAttributeMaxDynamicSharedMemorySize, GST);
    cudaFuncSetAttribute(dhb_tf32, cudaFuncAttributeMaxDynamicSharedMemorySize, DB_SMEM);
    cudaFuncSetAttribute(cheb_tf32, cudaFuncAttributeMaxDynamicSharedMemorySize, CH_SMEM);
    cudaFuncSetAttribute(o_tf32, cudaFuncAttributeMaxDynamicSharedMemorySize, O_SMEM);

    gates_mm<<<dim3(8, 4), 256>>>(x, Wa, Wb, Wal);            // 0 (writes g_xr too)
    gates_ep<<<192, 256>>>(A_log, dt_b, bb, bal);             // 1
    cs_kernel<<<1, 256>>>();                                  // 2
    proj_tf32<<<dim3(48, 8, 2), 256, GST>>>(Wq, Wk, Wv, Wg);  // 3  <- ncu capture
    conv_all<<<16384, 256>>>(conv_q, conv_k, conv_v);         // 4
    dhb_tf32<<<256, 256, DB_SMEM>>>();                        // 5
    scan_kernel<<<1024, 256>>>();                             // 6
    cheb_tf32<<<256, 256, CH_SMEM>>>();                       // 7
    o_tf32<<<256, 256, O_SMEM>>>(norm_w);                     // 8
    sgemm_tf32<<<dim3(16, 8, 2), 256, GST>>>(on, Wo);         // 9
    add_out<<<2048, 256>>>(out);                              // 10
}

// round 17
// speedup vs baseline: 1.0204x; 1.0204x over previous
#include <cuda_runtime.h>
#include <math.h>

#define LSEQ 1024
#define DMODEL 2048
#define NHQ 16
#define NHK 8
#define DHEAD 128
#define NCHUNK 16
#define CLEN 64
#define NITER 30
#define RIDGE_C 0.02f

__device__ __forceinline__ unsigned f2tf(float f) {
    unsigned r; asm("cvt.rna.tf32.f32 %0, %1;" : "=r"(r) : "f"(f)); return r;
}
__device__ __forceinline__ float f2tff(float f) {
    unsigned r; asm("cvt.rna.tf32.f32 %0, %1;" : "=r"(r) : "f"(f));
    return __uint_as_float(r);
}
#define MMA_TF32(acc, a0, a1, a2, a3, b0, b1)                               \
    asm volatile(                                                           \
        "mma.sync.aligned.m16n8k8.row.col.f32.tf32.tf32.f32 "               \
        "{%0,%1,%2,%3}, {%4,%5,%6,%7}, {%8,%9}, {%0,%1,%2,%3};"             \
        : "+f"((acc)[0]), "+f"((acc)[1]), "+f"((acc)[2]), "+f"((acc)[3])    \
        : "r"(a0), "r"(a1), "r"(a2), "r"(a3), "r"(b0), "r"(b1))

__device__ __forceinline__ void cp_async16(void* smem_dst, const void* gmem_src) {
    unsigned sa = (unsigned)__cvta_generic_to_shared(smem_dst);
    asm volatile("cp.async.ca.shared.global [%0], [%1], 16;" :: "r"(sa), "l"(gmem_src));
}
__device__ __forceinline__ void cp_commit() {
    asm volatile("cp.async.commit_group;");
}
template<int NWAIT>
__device__ __forceinline__ void cp_wait() {
    asm volatile("cp.async.wait_group %0;" :: "n"(NWAIT));
}

// ---------------- device scratch ----------------
__device__ float g_pqp[2][LSEQ * 2048];
__device__ float g_pkp[2][LSEQ * 1024];
__device__ float g_pvp[2][LSEQ * 1024];
__device__ float g_gpp[2][LSEQ * 2048];
__device__ float g_outp[2][LSEQ * 2048];
__device__ float g_q [LSEQ * 2048];
__device__ float g_k [LSEQ * 1024];
__device__ float g_v [LSEQ * 1024];
__device__ float g_gpart[4][LSEQ][48];
__device__ float g_glog [LSEQ * NHQ];
__device__ float g_beta [LSEQ * NHQ];
__device__ float g_alpha[LSEQ * NHQ];
__device__ float g_cs[NHQ * NCHUNK * CLEN];
__device__ float g_G [NHQ * NCHUNK];
__device__ float g_dgv[NHQ * NCHUNK];
__device__ float g_dH[NHQ * NCHUNK * DHEAD * DHEAD];
__device__ float g_dB[NHQ * NCHUNK * DHEAD * DHEAD];
__device__ float g_H0[NHQ * NCHUNK * DHEAD * DHEAD];
__device__ float g_B0[NHQ * NCHUNK * DHEAD * DHEAD];
__device__ float g_X [NHQ * NCHUNK * DHEAD * DHEAD];
__device__ float g_on[LSEQ * 2048];
__device__ float g_xr [LSEQ * 2048];

// -- tf32 GEMM: 128x128 tile, KTILE=16, m16n8k8, 3-stage cp.async (R15) --
#define GST (3 * (128 * 20 + 16 * 136) * 4)   // 56832 bytes

struct SmemTF32 {
    float As[3][128][20];
    float Bs[3][16][136];
};

__device__ __forceinline__ void gemm_tf32_core(
    const float* __restrict__ A, const float* __restrict__ B, float* __restrict__ C,
    int N, int Kfull, int koff, int klen, int bm, int bn, SmemTF32& s)
{
    const int tid = threadIdx.x;
    const int warp = tid >> 5, lane = tid & 31;
    const int wy = warp >> 1, wx = warp & 1;
    const int m0 = wy * 32, n0 = wx * 64;
    const int r = lane >> 2, c = lane & 3;

    float acc[2][8][4];
#pragma unroll
    for (int mt = 0; mt < 2; mt++)
#pragma unroll
        for (int nt = 0; nt < 8; nt++)
#pragma unroll
            for (int i = 0; i < 4; i++) acc[mt][nt][i] = 0.f;

    const int arow0 = tid >> 2;
    const int aq = (tid & 3) * 4;
    const int bk0 = tid >> 5;
    const int bn4 = (tid & 31) * 4;

    const float* Ap0 = A + (size_t)(bm + arow0) * Kfull + koff + aq;
    const float* Ap1 = A + (size_t)(bm + arow0 + 64) * Kfull + koff + aq;
    const float* Bp0 = B + (size_t)(koff + bk0) * N + bn + bn4;
    const float* Bp1 = B + (size_t)(koff + bk0 + 8) * N + bn + bn4;

    const int nk = klen >> 4;
    {
        cp_async16(&s.As[0][arow0][aq], Ap0);
        cp_async16(&s.As[0][arow0 + 64][aq], Ap1);
        cp_async16(&s.Bs[0][bk0][bn4], Bp0);
        cp_async16(&s.Bs[0][bk0 + 8][bn4], Bp1);
        cp_commit();
        if (nk > 1) {
            cp_async16(&s.As[1][arow0][aq], Ap0 + 16);
            cp_async16(&s.As[1][arow0 + 64][aq], Ap1 + 16);
            cp_async16(&s.Bs[1][bk0][bn4], Bp0 + (size_t)16 * N);
            cp_async16(&s.Bs[1][bk0 + 8][bn4], Bp1 + (size_t)16 * N);
            cp_commit();
        }
    }

    for (int t = 0; t < nk; t++) {
        cp_wait<1>();
        __syncthreads();
        if (t + 2 < nk) {
            const int nb = (t + 2) % 3;
            int k0 = (t + 2) << 4;
            cp_async16(&s.As[nb][arow0][aq], Ap0 + k0);
            cp_async16(&s.As[nb][arow0 + 64][aq], Ap1 + k0);
            cp_async16(&s.Bs[nb][bk0][bn4], Bp0 + (size_t)k0 * N);
            cp_async16(&s.Bs[nb][bk0 + 8][bn4], Bp1 + (size_t)k0 * N);
            cp_commit();
        }
        const int cur = t % 3;
#pragma unroll
        for (int ks = 0; ks < 2; ks++) {
            const int kk = ks * 8;
            unsigned a[2][4];
#pragma unroll
            for (int mt = 0; mt < 2; mt++) {
                int mr = m0 + mt * 16;
                a[mt][0] = __float_as_uint(s.As[cur][mr + r][kk + c]);
                a[mt][1] = __float_as_uint(s.As[cur][mr + r + 8][kk + c]);
                a[mt][2] = __float_as_uint(s.As[cur][mr + r][kk + c + 4]);
                a[mt][3] = __float_as_uint(s.As[cur][mr + r + 8][kk + c + 4]);
            }
#pragma unroll
            for (int nt = 0; nt < 8; nt++) {
                unsigned b0 = f2tf(s.Bs[cur][kk + c][n0 + nt * 8 + r]);
                unsigned b1 = f2tf(s.Bs[cur][kk + c + 4][n0 + nt * 8 + r]);
#pragma unroll
                for (int mt = 0; mt < 2; mt++)
                    MMA_TF32(acc[mt][nt], a[mt][0], a[mt][1], a[mt][2], a[mt][3], b0, b1);
            }
        }
    }
#pragma unroll
    for (int mt = 0; mt < 2; mt++) {
        int mr = bm + m0 + mt * 16 + r;
#pragma unroll
        for (int nt = 0; nt < 8; nt++) {
            int col = bn + n0 + nt * 8 + 2 * c;
            *(float2*)(C + (size_t)mr * N + col) =
                make_float2(acc[mt][nt][0], acc[mt][nt][1]);
            *(float2*)(C + (size_t)(mr + 8) * N + col) =
                make_float2(acc[mt][nt][2], acc[mt][nt][3]);
        }
    }
}

__global__ __launch_bounds__(256) void sgemm_tf32(
    const float* __restrict__ A, const float* __restrict__ B)
{
    extern __shared__ char smraw[];
    const int kz = blockIdx.z;
    gemm_tf32_core(A, B, g_outp[kz], 2048, 2048, kz * 1024, 1024,
                   blockIdx.y * 128, blockIdx.x * 128, *(SmemTF32*)smraw);
}

__global__ void add_out(float* __restrict__ out)
{
    int i4 = blockIdx.x * 256 + threadIdx.x;
    float4 a = *(const float4*)(g_outp[0] + (size_t)i4 * 4);
    float4 b = *(const float4*)(g_outp[1] + (size_t)i4 * 4);
    *(float4*)(out + (size_t)i4 * 4) =
        make_float4(a.x + b.x, a.y + b.y, a.z + b.z, a.w + b.w);
}

__global__ __launch_bounds__(256) void proj_tf32(
    const float* __restrict__ Wq, const float* __restrict__ Wk,
    const float* __restrict__ Wv, const float* __restrict__ Wg)
{
    extern __shared__ char smraw[];
    const int bx = blockIdx.x, kz = blockIdx.z;
    const float* B; float* C; int N, bn;
    if (bx < 16)      { B = Wq; C = g_pqp[kz]; N = 2048; bn = bx * 128; }
    else if (bx < 24) { B = Wk; C = g_pkp[kz]; N = 1024; bn = (bx - 16) * 128; }
    else if (bx < 32) { B = Wv; C = g_pvp[kz]; N = 1024; bn = (bx - 24) * 128; }
    else              { B = Wg; C = g_gpp[kz]; N = 2048; bn = (bx - 32) * 128; }
    gemm_tf32_core(g_xr, B, C, N, DMODEL, kz * 1024, 1024,
                   blockIdx.y * 128, bn, *(SmemTF32*)smraw);
}

// ------- gates as GEMM (fp32) + side-effect: write tf32-rounded x -------
__global__ __launch_bounds__(256) void gates_mm(
    const float* __restrict__ x, const float* __restrict__ Wa,
    const float* __restrict__ Wb, const float* __restrict__ Wal)
{
    __shared__ float xs[16][132];
    __shared__ float Ws[16][52];
    const int bm = blockIdx.x * 128;
    const int k0 = blockIdx.y * 512;
    const int tid = threadIdx.x;
    const int row = tid >> 1, kq = (tid & 1) * 8;
    const int wk = tid >> 4, wh = tid & 15;
    const int ty = tid >> 3, tx = tid & 7;

    float acc[4][6];
#pragma unroll
    for (int i = 0; i < 4; i++)
#pragma unroll
        for (int j = 0; j < 6; j++) acc[i][j] = 0.f;

    for (int kt = 0; kt < 512; kt += 16) {
        const int kb = k0 + kt;
        float4 v0 = *(const float4*)(x + (size_t)(bm + row) * DMODEL + kb + kq);
        float4 v1 = *(const float4*)(x + (size_t)(bm + row) * DMODEL + kb + kq + 4);
        xs[kq + 0][row] = v0.x; xs[kq + 1][row] = v0.y;
        xs[kq + 2][row] = v0.z; xs[kq + 3][row] = v0.w;
        xs[kq + 4][row] = v1.x; xs[kq + 5][row] = v1.y;
        xs[kq + 6][row] = v1.z; xs[kq + 7][row] = v1.w;
        float4 r0 = make_float4(f2tff(v0.x), f2tff(v0.y), f2tff(v0.z), f2tff(v0.w));
        float4 r1 = make_float4(f2tff(v1.x), f2tff(v1.y), f2tff(v1.z), f2tff(v1.w));
        *(float4*)(g_xr + (size_t)(bm + row) * DMODEL + kb + kq)     = r0;
        *(float4*)(g_xr + (size_t)(bm + row) * DMODEL + kb + kq + 4) = r1;
        Ws[wk][wh]      = Wa[(size_t)(kb + wk) * NHQ + wh];
        Ws[wk][16 + wh] = Wb[(size_t)(kb + wk) * NHQ + wh];
        Ws[wk][32 + wh] = Wal[(size_t)(kb + wk) * NHQ + wh];
        __syncthreads();
#pragma unroll
        for (int kk = 0; kk < 16; kk++) {
            float a[4], b[6];
#pragma unroll
            for (int i = 0; i < 4; i++) a[i] = xs[kk][ty * 4 + i];
#pragma unroll
            for (int j = 0; j < 6; j++) b[j] = Ws[kk][tx * 6 + j];
#pragma unroll
            for (int i = 0; i < 4; i++)
#pragma unroll
                for (int j = 0; j < 6; j++) acc[i][j] += a[i] * b[j];
        }
        __syncthreads();
    }
#pragma unroll
    for (int i = 0; i < 4; i++)
#pragma unroll
        for (int j = 0; j < 6; j++)
            g_gpart[blockIdx.y][bm + ty * 4 + i][tx * 6 + j] = acc[i][j];
}

__global__ void gates_ep(
    const float* __restrict__ A_log, const float* __restrict__ dt_bias,
    const float* __restrict__ bb, const float* __restrict__ bal)
{
    int idx = blockIdx.x * 256 + threadIdx.x;
    if (idx >= LSEQ * 48) return;
    int t = idx / 48, j = idx % 48;
    float s = g_gpart[0][t][j] + g_gpart[1][t][j]
            + g_gpart[2][t][j] + g_gpart[3][t][j];
    if (j < 16) {
        float z = s + dt_bias[j];
        float sp = (z > 20.f) ? z : log1pf(expf(z));
        g_glog[t * NHQ + j] = -expf(A_log[j]) * sp;
    } else if (j < 32) {
        int h = j - 16;
        g_beta[t * NHQ + h] = 1.f / (1.f + expf(-(s + bb[h])));
    } else {
        int h = j - 32;
        g_alpha[t * NHQ + h] = 1.f / (1.f + expf(-(s + bal[h])));
    }
}

// ------ fused conv(4)+silu for q,k,v; sums the two K-split partials ------
__global__ void conv_all(const float* __restrict__ wq, const float* __restrict__ wk,
                         const float* __restrict__ wv)
{
    int idx = blockIdx.x * 256 + threadIdx.x;
    const float *in0, *in1, *w; float* out; int C; float scale; int id2;
    if (idx < LSEQ * 2048) {
        in0 = g_pqp[0]; in1 = g_pqp[1]; w = wq; out = g_q; C = 2048;
        scale = 0.08838834764831843f; id2 = idx;
    } else if (idx < LSEQ * 2048 + LSEQ * 1024) {
        in0 = g_pkp[0]; in1 = g_pkp[1]; w = wk; out = g_k; C = 1024;
        scale = 1.f; id2 = idx - LSEQ * 2048;
    } else {
        in0 = g_pvp[0]; in1 = g_pvp[1]; w = wv; out = g_v; C = 1024;
        scale = 1.f; id2 = idx - LSEQ * 2048 - LSEQ * 1024;
    }
    int t = id2 / C, c = id2 % C;
    float s = 0.f;
#pragma unroll
    for (int j = 0; j < 4; j++) {
        int tj = t - 3 + j;
        if (tj >= 0) {
            size_t o = (size_t)tj * C + c;
            s += (in0[o] + in1[o]) * w[c * 4 + j];
        }
    }
    out[id2] = s / (1.f + expf(-s)) * scale;
}

// ---------------- per-chunk cumsum ----------------
__global__ void cs_kernel()
{
    int id = threadIdx.x;
    int h = id >> 4, n = id & 15;
    float s = 0.f;
    for (int c = 0; c < CLEN; c++) {
        s += g_glog[(n * CLEN + c) * NHQ + h];
        g_cs[(h * NCHUNK + n) * CLEN + c] = s;
    }
    g_G[h * NCHUNK + n] = s;
    g_dgv[h * NCHUNK + n] = expf(s);
}

// -------- dH / dB gram increments via tf32 mma --------
#define DB_PAD 132
#define DB_SMEM ((2 * 64 * DB_PAD + 64) * 4)

__global__ __launch_bounds__(256, 1) void dhb_tf32()
{
    extern __shared__ float sm[];
    float* ksf = sm;
    float* vsf = sm + 64 * DB_PAD;
    float* ws  = sm + 2 * 64 * DB_PAD;
    const int mat = blockIdx.x;
    const int h = mat >> 4, n = mat & 15, hk = h >> 1;
    const int tid = threadIdx.x;
    for (int i = tid; i < CLEN * DHEAD; i += 256) {
        int c = i >> 7, d = i & 127;
        int t = n * CLEN + c;
        ksf[c * DB_PAD + d] = g_k[t * 1024 + hk * DHEAD + d];
        vsf[c * DB_PAD + d] = g_v[t * 1024 + hk * DHEAD + d];
    }
    if (tid < CLEN) {
        float G = g_G[mat];
        float cs = g_cs[mat * CLEN + tid];
        ws[tid] = expf(G - cs) * g_beta[(n * CLEN + tid) * NHQ + h];
    }
    __syncthreads();

    const int warp = tid >> 5, lane = tid & 31;
    const int m0 = warp * 16;
    const int fr = lane >> 2, fc = lane & 3;

    float accH[16][4], accB[16][4];
#pragma unroll
    for (int nt = 0; nt < 16; nt++)
#pragma unroll
        for (int i = 0; i < 4; i++) { accH[nt][i] = 0.f; accB[nt][i] = 0.f; }

#pragma unroll 1
    for (int ks8 = 0; ks8 < 8; ks8++) {
        const int kk = ks8 * 8;
        float w0 = ws[kk + fc], w1 = ws[kk + fc + 4];
        unsigned a0 = f2tf(w0 * ksf[(kk + fc) * DB_PAD + m0 + fr]);
        unsigned a1 = f2tf(w0 * ksf[(kk + fc) * DB_PAD + m0 + fr + 8]);
        unsigned a2 = f2tf(w1 * ksf[(kk + fc + 4) * DB_PAD + m0 + fr]);
        unsigned a3 = f2tf(w1 * ksf[(kk + fc + 4) * DB_PAD + m0 + fr + 8]);
#pragma unroll
        for (int nt = 0; nt < 16; nt++) {
            int cn = nt * 8 + fr;
            unsigned bh0 = f2tf(ksf[(kk + fc) * DB_PAD + cn]);
            unsigned bh1 = f2tf(ksf[(kk + fc + 4) * DB_PAD + cn]);
            MMA_TF32(accH[nt], a0, a1, a2, a3, bh0, bh1);
            unsigned bv0 = f2tf(vsf[(kk + fc) * DB_PAD + cn]);
            unsigned bv1 = f2tf(vsf[(kk + fc + 4) * DB_PAD + cn]);
            MMA_TF32(accB[nt], a0, a1, a2, a3, bv0, bv1);
        }
    }
    size_t base = (size_t)mat * DHEAD * DHEAD;
#pragma unroll
    for (int nt = 0; nt < 16; nt++) {
        int col = nt * 8 + 2 * fc;
        size_t r0 = base + (size_t)(m0 + fr) * 128 + col;
        size_t r1 = base + (size_t)(m0 + fr + 8) * 128 + col;
        *(float2*)&g_dH[r0] = make_float2(accH[nt][0], accH[nt][1]);
        *(float2*)&g_dH[r1] = make_float2(accH[nt][2], accH[nt][3]);
        *(float2*)&g_dB[r0] = make_float2(accB[nt][0], accB[nt][1]);
        *(float2*)&g_dB[r1] = make_float2(accB[nt][2], accB[nt][3]);
    }
}

// ---------------- inter-chunk scan ----------------
__global__ void scan_kernel()
{
    int idx = blockIdx.x * blockDim.x + threadIdx.x;
    int h = idx >> 14;
    int rem = idx & 16383;
    float hc = 0.f, bc = 0.f;
    for (int n = 0; n < NCHUNK; n++) {
        size_t off = (size_t)(h * NCHUNK + n) * 16384 + rem;
        g_H0[off] = hc;
        g_B0[off] = bc;
        float g = g_dgv[h * NCHUNK + n];
        hc = g * hc + g_dH[off];
        bc = g * bc + g_dB[off];
    }
}

// ------- Chebyshev solve: warp tile 64x32 (2m x 4n warp grid) -------
#define CH_APAD 132
#define CH_DPAD 136
#define CH_SMEM (128*CH_APAD*4 + 128*CH_DPAD*4)

__global__ __launch_bounds__(256, 1) void cheb_tf32()
{
    extern __shared__ char smemraw[];
    unsigned (*Ash)[CH_APAD] = (unsigned(*)[CH_APAD])smemraw;
    float (*dsh)[CH_DPAD] = (float(*)[CH_DPAD])(smemraw + 128 * CH_APAD * 4);
    __shared__ float red[128];
    __shared__ float s_lmax;

    const int mat = blockIdx.x;
    const int tid = threadIdx.x;
    const int warp = tid >> 5, lane = tid & 31;
    const int wm = warp >> 2, wn = warp & 3;   // warp grid 2(m) x 4(n)
    const int fr = lane >> 2, fc = lane & 3;
    const float* H0 = g_H0 + (size_t)mat * 16384;
    const float* B0p = g_B0 + (size_t)mat * 16384;

    for (int i = tid; i < 16384; i += 256) {
        int row = i >> 7, col = i & 127;
        float v = H0[i];
        if (row == col) { v += RIDGE_C; red[row] = v; }
        Ash[row][col] = f2tf(v);
    }
    __syncthreads();
    for (int s = 64; s > 0; s >>= 1) {
        if (tid < s) red[tid] += red[tid + s];
        __syncthreads();
    }
    if (tid == 0) s_lmax = red[0];
    __syncthreads();

    const float lmax = s_lmax;
    const float theta = (lmax + RIDGE_C) * 0.5f;
    const float delta = (lmax - RIDGE_C) * 0.5f;
    const float sigma1 = theta / delta;
    float rho = 1.f / sigma1;
    const float inv_theta = 1.f / theta;

    // r, x in fragment layout: rows wm*64+mt*16+{fr,fr+8}, cols wn*32+nt*8+2fc+{0,1}
    float r_[4][4][4], x_[4][4][4];
#pragma unroll
    for (int mt = 0; mt < 4; mt++)
#pragma unroll
        for (int nt = 0; nt < 4; nt++) {
            int ro = wm * 64 + mt * 16 + fr;
            int co = wn * 32 + nt * 8 + 2 * fc;
            float2 b0 = *(const float2*)&B0p[ro * 128 + co];
            float2 b1 = *(const float2*)&B0p[(ro + 8) * 128 + co];
            r_[mt][nt][0] = b0.x; r_[mt][nt][1] = b0.y;
            r_[mt][nt][2] = b1.x; r_[mt][nt][3] = b1.y;
            x_[mt][nt][0] = 0.f; x_[mt][nt][1] = 0.f;
            x_[mt][nt][2] = 0.f; x_[mt][nt][3] = 0.f;
            *(float2*)&dsh[ro][co] = make_float2(
                f2tff(b0.x * inv_theta), f2tff(b0.y * inv_theta));
            *(float2*)&dsh[ro + 8][co] = make_float2(
                f2tff(b1.x * inv_theta), f2tff(b1.y * inv_theta));
        }
    __syncthreads();

    for (int it = 0; it < NITER; it++) {
        float acc[4][4][4];
#pragma unroll
        for (int mt = 0; mt < 4; mt++)
#pragma unroll
            for (int nt = 0; nt < 4; nt++) {
                acc[mt][nt][0] = 0.f; acc[mt][nt][1] = 0.f;
                acc[mt][nt][2] = 0.f; acc[mt][nt][3] = 0.f;
            }
#pragma unroll 1
        for (int ks = 0; ks < 16; ks++) {
            const int kk = ks * 8;
            unsigned a[4][4];
#pragma unroll
            for (int mt = 0; mt < 4; mt++) {
                int mr = wm * 64 + mt * 16;
                a[mt][0] = Ash[mr + fr][kk + fc];
                a[mt][1] = Ash[mr + fr + 8][kk + fc];
                a[mt][2] = Ash[mr + fr][kk + fc + 4];
                a[mt][3] = Ash[mr + fr + 8][kk + fc + 4];
            }
#pragma unroll
            for (int nt = 0; nt < 4; nt++) {
                int cn = wn * 32 + nt * 8 + fr;
                unsigned b0 = __float_as_uint(dsh[kk + fc][cn]);
                unsigned b1 = __float_as_uint(dsh[kk + fc + 4][cn]);
#pragma unroll
                for (int mt = 0; mt < 4; mt++)
                    MMA_TF32(acc[mt][nt], a[mt][0], a[mt][1], a[mt][2], a[mt][3], b0, b1);
            }
        }
        __syncthreads();

        float rho_n = 1.f / (2.f * sigma1 - rho);
        float c1 = rho_n * rho;
        float c2 = 2.f * rho_n / delta;
#pragma unroll
        for (int mt = 0; mt < 4; mt++)
#pragma unroll
            for (int nt = 0; nt < 4; nt++) {
                int ro = wm * 64 + mt * 16 + fr;
                int co = wn * 32 + nt * 8 + 2 * fc;
                float2 d0 = *(float2*)&dsh[ro][co];
                float2 d1 = *(float2*)&dsh[ro + 8][co];
                x_[mt][nt][0] += d0.x; x_[mt][nt][1] += d0.y;
                x_[mt][nt][2] += d1.x; x_[mt][nt][3] += d1.y;
                r_[mt][nt][0] -= acc[mt][nt][0]; r_[mt][nt][1] -= acc[mt][nt][1];
                r_[mt][nt][2] -= acc[mt][nt][2]; r_[mt][nt][3] -= acc[mt][nt][3];
                d0.x = f2tff(c1 * d0.x + c2 * r_[mt][nt][0]);
                d0.y = f2tff(c1 * d0.y + c2 * r_[mt][nt][1]);
                d1.x = f2tff(c1 * d1.x + c2 * r_[mt][nt][2]);
                d1.y = f2tff(c1 * d1.y + c2 * r_[mt][nt][3]);
                *(float2*)&dsh[ro][co]     = d0;
                *(float2*)&dsh[ro + 8][co] = d1;
            }
        rho = rho_n;
        __syncthreads();
    }

    float* Xp = g_X + (size_t)mat * 16384;
#pragma unroll
    for (int mt = 0; mt < 4; mt++)
#pragma unroll
        for (int nt = 0; nt < 4; nt++) {
            int ro = wm * 64 + mt * 16 + fr;
            int co = wn * 32 + nt * 8 + 2 * fc;
            *(float2*)&Xp[ro * 128 + co] =
                make_float2(x_[mt][nt][0], x_[mt][nt][1]);
            *(float2*)&Xp[(ro + 8) * 128 + co] =
                make_float2(x_[mt][nt][2], x_[mt][nt][3]);
        }
}

// ---- o: scores + inter + intra via tf32 mma, alpha*v, gated RMSNorm ----
#define OP 132
#define O_SMEM ((3 * 64 * OP + 128 * OP + 64 * OP) * 4)

__global__ __launch_bounds__(256, 1) void o_tf32(const float* __restrict__ norm_w)
{
    extern __shared__ float sm[];
    float* qs = sm;
    float* ks = sm + 64 * OP;
    float* vs = sm + 2 * 64 * OP;
    float* Xs = sm + 3 * 64 * OP;
    float* Os = sm + 3 * 64 * OP + 128 * OP;
    __shared__ float csh[CLEN], bsh[CLEN], ash[CLEN], expc[CLEN];
    const int mat = blockIdx.x;
    const int h = mat >> 4, n = mat & 15, hk = h >> 1;
    const int tid = threadIdx.x;
    const int warp = tid >> 5, lane = tid & 31;
    const int fr = lane >> 2, fc = lane & 3;

    for (int i = tid; i < CLEN * DHEAD; i += 256) {
        int c = i >> 7, d = i & 127;
        int t = n * CLEN + c;
        qs[c * OP + d] = g_q[t * 2048 + h * DHEAD + d];
        ks[c * OP + d] = g_k[t * 1024 + hk * DHEAD + d];
        vs[c * OP + d] = g_v[t * 1024 + hk * DHEAD + d];
    }
    for (int i = tid; i < 16384; i += 256) {
        int row = i >> 7, col = i & 127;
        Xs[row * OP + col] = g_X[(size_t)mat * 16384 + i];
    }
    if (tid < CLEN) {
        float cv = g_cs[mat * CLEN + tid];
        csh[tid] = cv;
        expc[tid] = expf(cv);
        int t = n * CLEN + tid;
        bsh[tid] = g_beta[t * NHQ + h];
        ash[tid] = g_alpha[t * NHQ + h];
    }
    __syncthreads();

    {
        const int m0 = (warp & 3) * 16, n0 = (warp >> 2) * 32;
        float sc[4][4];
#pragma unroll
        for (int nt = 0; nt < 4; nt++)
#pragma unroll
            for (int i = 0; i < 4; i++) sc[nt][i] = 0.f;
#pragma unroll 1
        for (int ks8 = 0; ks8 < 16; ks8++) {
            const int kk = ks8 * 8;
            unsigned a0 = f2tf(qs[(m0 + fr) * OP + kk + fc]);
            unsigned a1 = f2tf(qs[(m0 + fr + 8) * OP + kk + fc]);
            unsigned a2 = f2tf(qs[(m0 + fr) * OP + kk + fc + 4]);
            unsigned a3 = f2tf(qs[(m0 + fr + 8) * OP + kk + fc + 4]);
#pragma unroll
            for (int nt = 0; nt < 4; nt++) {
                int j = n0 + nt * 8 + fr;
                unsigned b0 = f2tf(ks[j * OP + kk + fc]);
                unsigned b1 = f2tf(ks[j * OP + kk + fc + 4]);
                MMA_TF32(sc[nt], a0, a1, a2, a3, b0, b1);
            }
        }
#pragma unroll
        for (int nt = 0; nt < 4; nt++) {
            int j0 = n0 + nt * 8 + 2 * fc;
            int c0 = m0 + fr, c1 = m0 + fr + 8;
#pragma unroll
            for (int e = 0; e < 4; e++) {
                int c = (e < 2) ? c0 : c1;
                int j = j0 + (e & 1);
                float v = 0.f;
                if (j <= c) v = sc[nt][e] * expf(csh[c] - csh[j]) * bsh[j];
                Os[c * OP + j] = v;
            }
        }
    }
    __syncthreads();

    {
        const int m0 = (warp & 3) * 16, n0 = (warp >> 2) * 64;
        float oa[8][4];
#pragma unroll
        for (int nt = 0; nt < 8; nt++)
#pragma unroll
            for (int i = 0; i < 4; i++) oa[nt][i] = 0.f;
        float e0 = expc[m0 + fr], e1 = expc[m0 + fr + 8];
#pragma unroll 1
        for (int ks8 = 0; ks8 < 16; ks8++) {
            const int kk = ks8 * 8;
            unsigned a0 = f2tf(qs[(m0 + fr) * OP + kk + fc] * e0);
            unsigned a1 = f2tf(qs[(m0 + fr + 8) * OP + kk + fc] * e1);
            unsigned a2 = f2tf(qs[(m0 + fr) * OP + kk + fc + 4] * e0);
            unsigned a3 = f2tf(qs[(m0 + fr + 8) * OP + kk + fc + 4] * e1);
#pragma unroll
            for (int nt = 0; nt < 8; nt++) {
                int cn = n0 + nt * 8 + fr;
                unsigned b0 = f2tf(Xs[(kk + fc) * OP + cn]);
                unsigned b1 = f2tf(Xs[(kk + fc + 4) * OP + cn]);
                MMA_TF32(oa[nt], a0, a1, a2, a3, b0, b1);
            }
        }
#pragma unroll 1
        for (int ks8 = 0; ks8 < 8; ks8++) {
            const int kk = ks8 * 8;
            unsigned a0 = f2tf(Os[(m0 + fr) * OP + kk + fc]);
            unsigned a1 = f2tf(Os[(m0 + fr + 8) * OP + kk + fc]);
            unsigned a2 = f2tf(Os[(m0 + fr) * OP + kk + fc + 4]);
            unsigned a3 = f2tf(Os[(m0 + fr + 8) * OP + kk + fc + 4]);
#pragma unroll
            for (int nt = 0; nt < 8; nt++) {
                int cn = n0 + nt * 8 + fr;
                unsigned b0 = f2tf(vs[(kk + fc) * OP + cn]);
                unsigned b1 = f2tf(vs[(kk + fc + 4) * OP + cn]);
                MMA_TF32(oa[nt], a0, a1, a2, a3, b0, b1);
            }
        }
        __syncthreads();
        int c0 = m0 + fr, c1 = m0 + fr + 8;
        float al0 = ash[c0], al1 = ash[c1];
#pragma unroll
        for (int nt = 0; nt < 8; nt++) {
            int col = n0 + nt * 8 + 2 * fc;
            Os[c0 * OP + col]     = oa[nt][0] + al0 * vs[c0 * OP + col];
            Os[c0 * OP + col + 1] = oa[nt][1] + al0 * vs[c0 * OP + col + 1];
            Os[c1 * OP + col]     = oa[nt][2] + al1 * vs[c1 * OP + col];
            Os[c1 * OP + col + 1] = oa[nt][3] + al1 * vs[c1 * OP + col + 1];
        }
    }
    __syncthreads();

    {
        const int ty = warp, tx = lane;
        const int f0 = tx * 4;
        float4 nw = *(const float4*)(norm_w + f0);
#pragma unroll
        for (int i = 0; i < 8; i++) {
            int c = ty * 8 + i;
            int t = n * CLEN + c;
            float4 ov = *(const float4*)&Os[c * OP + f0];
            float ss = ov.x * ov.x + ov.y * ov.y + ov.z * ov.z + ov.w * ov.w;
#pragma unroll
            for (int off = 16; off > 0; off >>= 1)
                ss += __shfl_xor_sync(0xFFFFFFFFu, ss, off);
            float rms = rsqrtf(ss * (1.f / 128.f) + 1e-6f);
            size_t go = (size_t)t * 2048 + h * 128 + f0;
            float4 g0 = *(const float4*)(g_gpp[0] + go);
            float4 g1 = *(const float4*)(g_gpp[1] + go);
            float4 gw = make_float4(g0.x + g1.x, g0.y + g1.y,
                                    g0.z + g1.z, g0.w + g1.w);
            float4 o;
            o.x = f2tff(ov.x * rms * nw.x * (gw.x / (1.f + expf(-gw.x))));
            o.y = f2tff(ov.y * rms * nw.y * (gw.y / (1.f + expf(-gw.y))));
            o.z = f2tff(ov.z * rms * nw.z * (gw.z / (1.f + expf(-gw.z))));
            o.w = f2tff(ov.w * rms * nw.w * (gw.w / (1.f + expf(-gw.w))));
            *(float4*)&g_on[go] = o;
        }
    }
}

// ---------------- launch ----------------
extern "C" void kernel_launch(void* const* d_in, const int* in_sizes, int n_in,
                              void* d_out, int out_size)
{
    const float* x      = (const float*)d_in[0];
    const float* Wq     = (const float*)d_in[1];
    const float* Wk     = (const float*)d_in[2];
    const float* Wv     = (const float*)d_in[3];
    const float* conv_q = (const float*)d_in[4];
    const float* conv_k = (const float*)d_in[5];
    const float* conv_v = (const float*)d_in[6];
    const float* Wa     = (const float*)d_in[7];
    const float* A_log  = (const float*)d_in[8];
    const float* dt_b   = (const float*)d_in[9];
    const float* Wb     = (const float*)d_in[10];
    const float* bb     = (const float*)d_in[11];
    const float* Wal    = (const float*)d_in[12];
    const float* bal    = (const float*)d_in[13];
    const float* Wg     = (const float*)d_in[14];
    const float* norm_w = (const float*)d_in[15];
    const float* Wo     = (const float*)d_in[16];
    float* out = (float*)d_out;

    float *on;
    cudaGetSymbolAddress((void**)&on, g_on);

    cudaFuncSetAttribute(proj_tf32, cudaFuncAttributeMaxDynamicSharedMemorySize, GST);
    cudaFuncSetAttribute(sgemm_tf32, cudaFuncAttributeMaxDynamicSharedMemorySize, GST);
    cudaFuncSetAttribute(dhb_tf32, cudaFuncAttributeMaxDynamicSharedMemorySize, DB_SMEM);
    cudaFuncSetAttribute(cheb_tf32, cudaFuncAttributeMaxDynamicSharedMemorySize, CH_SMEM);
    cudaFuncSetAttribute(o_tf32, cudaFuncAttributeMaxDynamicSharedMemorySize, O_SMEM);

    gates_mm<<<dim3(8, 4), 256>>>(x, Wa, Wb, Wal);            // 0 (writes g_xr too)
    gates_ep<<<192, 256>>>(A_log, dt_b, bb, bal);             // 1
    cs_kernel<<<1, 256>>>();                                  // 2
    proj_tf32<<<dim3(48, 8, 2), 256, GST>>>(Wq, Wk, Wv, Wg);  // 3
    conv_all<<<16384, 256>>>(conv_q, conv_k, conv_v);         // 4
    dhb_tf32<<<256, 256, DB_SMEM>>>();                        // 5
    scan_kernel<<<1024, 256>>>();                             // 6
    cheb_tf32<<<256, 256, CH_SMEM>>>();                       // 7
    o_tf32<<<256, 256, O_SMEM>>>(norm_w);                     // 8
    sgemm_tf32<<<dim3(16, 8, 2), 256, GST>>>(on, Wo);         // 9
    add_out<<<2048, 256>>>(out);                              // 10
}